// round 15
// baseline (speedup 1.0000x reference)
#include <cuda_runtime.h>
#include <math.h>

#define B_  4
#define C_  64
#define OC_ 64
#define H_  256
#define W_  256
#define HW_ 65536
#define CHW_ (C_*HW_)          // 4194304
#define TOT_ (B_*CHW_)         // 16777216
#define MAXOFF_ 64.0f

// ---------------- scratch (device globals, no allocation) ----------------
__device__ float2 g_offp[B_*C_*HW_];    // paired (oy, ox) per channel
__device__ float  g_mod [TOT_];         // modulator
__device__ float  g_out [TOT_];         // pre-BN output
__device__ double g_sum  [OC_];
__device__ double g_sumsq[OC_];
__device__ float  g_scale[OC_];
__device__ float  g_shift[OC_];

// ---------------- f32x2 helpers ----------------
typedef unsigned long long u64;

__device__ __forceinline__ u64 pk2(float lo, float hi) {
    u64 r;
    asm("mov.b64 %0, {%1, %2};" : "=l"(r) : "f"(lo), "f"(hi));
    return r;
}
__device__ __forceinline__ void upk2(u64 v, float &lo, float &hi) {
    asm("mov.b64 {%0, %1}, %2;" : "=f"(lo), "=f"(hi) : "l"(v));
}
__device__ __forceinline__ void fma2(u64 &d, u64 a, u64 b) {
    asm("fma.rn.f32x2 %0, %1, %2, %0;" : "+l"(d) : "l"(a), "l"(b));
}

__device__ __forceinline__ float clipoff(float v) {
    return fminf(fmaxf(v, -MAXOFF_), MAXOFF_);
}

// ==========================================================================
// Kernel A: fused depthwise 3x3 conv -> pointwise 64->192 GEMM (f32x2)
// One block per (row h, batch b). 256 threads. smem: dw tile + pw weights.
// ==========================================================================
__global__ __launch_bounds__(256) void fused_dw_pw(const float* __restrict__ x,
                                                   const float* __restrict__ dww,
                                                   const float* __restrict__ pww) {
    extern __shared__ float smA[];
    float* s_in = smA;                  // [64][256] dw result, 65536 B
    float* s_pw = smA + 64*256;         // [192][64] pw weights, 49152 B
    float* s_dw = s_pw + 192*64;        // [64*9] dw weights

    const int tid = threadIdx.x;
    const int h = blockIdx.x, b = blockIdx.y;

    for (int i = tid; i < 192*64; i += 256) s_pw[i] = pww[i];
    for (int i = tid; i < 576;    i += 256) s_dw[i] = dww[i];
    __syncthreads();

    // ---- phase 1: depthwise conv for this row, all channels, into smem ----
    {
        const int p = tid;                       // p == w (full row per block)
        const float* xb = x + b*CHW_ + h*W_ + p; // channel 0 base at (h,p)
        #pragma unroll 2
        for (int c = 0; c < 64; c++) {
            const float* wp = s_dw + c*9;
            const float* xp = xb + c*HW_;
            float acc = 0.f;
            #pragma unroll
            for (int ky = 0; ky < 3; ky++) {
                int yy = h + ky - 1;
                if ((unsigned)yy >= H_) continue;
                const float* row = xp + (ky-1)*W_;
                if (p > 0)     acc = fmaf(__ldg(row - 1), wp[ky*3+0], acc);
                               acc = fmaf(__ldg(row    ), wp[ky*3+1], acc);
                if (p < W_-1)  acc = fmaf(__ldg(row + 1), wp[ky*3+2], acc);
            }
            s_in[c*256 + p] = acc;
        }
    }
    __syncthreads();

    // ---- phase 2: 192x64 GEMM with f32x2, thread tile = 4 pixels x 8 outs ----
    const int pg = tid & 63;      // pixel group: pixels 4*pg .. 4*pg+3
    const int og = tid >> 6;      // output group 0..3
    const int hwb = h*W_ + pg*4;
    const u64* sin64 = (const u64*)s_in;

    #pragma unroll 1
    for (int t = 0; t < 6; t++) {
        const int obase = t*32 + og*8;
        u64 acc0[8], acc1[8];
        #pragma unroll
        for (int j = 0; j < 8; j++) { acc0[j] = 0ULL; acc1[j] = 0ULL; }

        #pragma unroll
        for (int c4 = 0; c4 < 16; c4++) {
            float4 wq[8];
            #pragma unroll
            for (int j = 0; j < 8; j++)
                wq[j] = *(const float4*)(s_pw + (obase+j)*64 + c4*4);
            #pragma unroll
            for (int cc = 0; cc < 4; cc++) {
                const int c = c4*4 + cc;
                u64 a0 = sin64[(c*256 + pg*4    ) >> 1];
                u64 a1 = sin64[(c*256 + pg*4 + 2) >> 1];
                #pragma unroll
                for (int j = 0; j < 8; j++) {
                    float w = (cc == 0) ? wq[j].x : (cc == 1) ? wq[j].y
                            : (cc == 2) ? wq[j].z : wq[j].w;
                    u64 wd = pk2(w, w);
                    fma2(acc0[j], a0, wd);
                    fma2(acc1[j], a1, wd);
                }
            }
        }

        if (t < 4) {
            // outputs 0..127 -> clipped offsets, paired (oy=out[2c], ox=out[2c+1])
            #pragma unroll
            for (int jj = 0; jj < 4; jj++) {
                const int c = (obase >> 1) + jj;
                float y0,y1,y2,y3, xo0,xo1,xo2,xo3;
                upk2(acc0[2*jj  ], y0,  y1 );  upk2(acc1[2*jj  ], y2,  y3 );
                upk2(acc0[2*jj+1], xo0, xo1);  upk2(acc1[2*jj+1], xo2, xo3);
                float4* dst = (float4*)(g_offp + (b*64 + c)*HW_ + hwb);
                dst[0] = make_float4(clipoff(y0), clipoff(xo0), clipoff(y1), clipoff(xo1));
                dst[1] = make_float4(clipoff(y2), clipoff(xo2), clipoff(y3), clipoff(xo3));
            }
        } else {
            // outputs 128..191 -> modulator = 2*sigmoid
            #pragma unroll
            for (int j = 0; j < 8; j++) {
                const int m = obase - 128 + j;
                float v0,v1,v2,v3;
                upk2(acc0[j], v0, v1);  upk2(acc1[j], v2, v3);
                v0 = 2.f / (1.f + expf(-v0));
                v1 = 2.f / (1.f + expf(-v1));
                v2 = 2.f / (1.f + expf(-v2));
                v3 = 2.f / (1.f + expf(-v3));
                *(float4*)(g_mod + (b*64 + m)*HW_ + hwb) = make_float4(v0,v1,v2,v3);
            }
        }
    }
}

// ==========================================================================
// Kernel B: bilinear sample * modulator -> 64x64 GEMM (f32x2) + bias
// ==========================================================================
__device__ __forceinline__ float samp(const float* __restrict__ xc, int y, int xx) {
    if ((unsigned)y < H_ && (unsigned)xx < W_) return __ldg(xc + y*W_ + xx);
    return 0.f;
}

__global__ __launch_bounds__(256) void sample_mm(const float* __restrict__ x,
                                                 const float* __restrict__ wgt,
                                                 const float* __restrict__ bias) {
    extern __shared__ float smB[];
    float* s_s = smB;                // [64][256] sampled values, 65536 B
    float* s_w = smB + 64*256;       // [64][64] weights
    float* s_b = s_w + 64*64;        // [64] bias

    const int tid = threadIdx.x;
    const int h = blockIdx.x, b = blockIdx.y;

    for (int i = tid; i < 64*64; i += 256) s_w[i] = wgt[i];
    if (tid < 64) s_b[tid] = bias[tid];

    // ---- phase 1: sampling (1 pixel per thread, all 64 channels) ----
    {
        const int p = tid;
        const int hw = h*W_ + p;
        const float* xb = x + b*CHW_;
        #pragma unroll 2
        for (int c = 0; c < 64; c++) {
            float2 off = g_offp[(b*64 + c)*HW_ + hw];
            float  m   = __ldg(g_mod + (b*64 + c)*HW_ + hw);
            float yf = (float)h + off.x;
            float xf = (float)p + off.y;
            float y0f = floorf(yf), x0f = floorf(xf);
            float wy = yf - y0f,    wx = xf - x0f;
            int y0 = (int)y0f, x0 = (int)x0f;
            const float* xc = xb + c*HW_;
            float v00 = samp(xc, y0,   x0  );
            float v01 = samp(xc, y0,   x0+1);
            float v10 = samp(xc, y0+1, x0  );
            float v11 = samp(xc, y0+1, x0+1);
            float v = (1.f-wy)*((1.f-wx)*v00 + wx*v01)
                    +      wy *((1.f-wx)*v10 + wx*v11);
            s_s[c*256 + p] = v * m;
        }
    }
    __syncthreads();

    // ---- phase 2: 64x64 GEMM with f32x2, thread tile = 4 pixels x 8 outs ----
    const int pg = tid & 63;
    const int og = tid >> 6;
    const int hwb = h*W_ + pg*4;
    const u64* ss64 = (const u64*)s_s;

    #pragma unroll 1
    for (int t = 0; t < 2; t++) {
        const int obase = t*32 + og*8;
        u64 acc0[8], acc1[8];
        #pragma unroll
        for (int j = 0; j < 8; j++) {
            u64 bb = pk2(s_b[obase+j], s_b[obase+j]);
            acc0[j] = bb; acc1[j] = bb;
        }

        #pragma unroll
        for (int c4 = 0; c4 < 16; c4++) {
            float4 wq[8];
            #pragma unroll
            for (int j = 0; j < 8; j++)
                wq[j] = *(const float4*)(s_w + (obase+j)*64 + c4*4);
            #pragma unroll
            for (int cc = 0; cc < 4; cc++) {
                const int c = c4*4 + cc;
                u64 a0 = ss64[(c*256 + pg*4    ) >> 1];
                u64 a1 = ss64[(c*256 + pg*4 + 2) >> 1];
                #pragma unroll
                for (int j = 0; j < 8; j++) {
                    float w = (cc == 0) ? wq[j].x : (cc == 1) ? wq[j].y
                            : (cc == 2) ? wq[j].z : wq[j].w;
                    u64 wd = pk2(w, w);
                    fma2(acc0[j], a0, wd);
                    fma2(acc1[j], a1, wd);
                }
            }
        }

        #pragma unroll
        for (int j = 0; j < 8; j++) {
            const int o = obase + j;
            float v0,v1,v2,v3;
            upk2(acc0[j], v0, v1);  upk2(acc1[j], v2, v3);
            *(float4*)(g_out + (b*64 + o)*HW_ + hwb) = make_float4(v0,v1,v2,v3);
        }
    }
}

// ---------------- stats ----------------
__global__ void zero_stats() {
    if (threadIdx.x < OC_) { g_sum[threadIdx.x] = 0.0; g_sumsq[threadIdx.x] = 0.0; }
}

__global__ __launch_bounds__(256) void stats_kernel() {
    const int b = blockIdx.x >> 6;
    const int o = blockIdx.x & 63;
    const float4* pl = (const float4*)(g_out + (b*64 + o)*HW_);
    float s = 0.f, s2 = 0.f;
    for (int i = threadIdx.x; i < HW_/4; i += 256) {
        float4 v = pl[i];
        s  += v.x + v.y + v.z + v.w;
        s2 += v.x*v.x + v.y*v.y + v.z*v.z + v.w*v.w;
    }
    __shared__ double sh0[256];
    __shared__ double sh1[256];
    sh0[threadIdx.x] = (double)s; sh1[threadIdx.x] = (double)s2;
    __syncthreads();
    for (int st = 128; st > 0; st >>= 1) {
        if (threadIdx.x < st) {
            sh0[threadIdx.x] += sh0[threadIdx.x+st];
            sh1[threadIdx.x] += sh1[threadIdx.x+st];
        }
        __syncthreads();
    }
    if (threadIdx.x == 0) {
        atomicAdd(&g_sum[o],   sh0[0]);
        atomicAdd(&g_sumsq[o], sh1[0]);
    }
}

__global__ void finalize_stats(const float* __restrict__ gamma, const float* __restrict__ beta) {
    const int o = threadIdx.x;
    if (o < OC_) {
        double N = (double)B_ * (double)HW_;
        double mean = g_sum[o] / N;
        double var  = g_sumsq[o] / N - mean*mean;
        double inv  = 1.0 / sqrt(var + 1e-5);
        double gsc  = inv * (double)gamma[o];
        g_scale[o] = (float)gsc;
        g_shift[o] = (float)((double)beta[o] - mean * gsc);
    }
}

// ---------------- BN affine + exact GELU (float4) ----------------
__global__ __launch_bounds__(256) void bn_gelu_kernel(float* __restrict__ out) {
    const int i = blockIdx.x*256 + threadIdx.x;     // float4 index
    const int o = (i >> 14) & 63;                   // 16384 float4 per plane
    const float sc = g_scale[o], sh = g_shift[o];
    float4 v = ((const float4*)g_out)[i];
    v.x = v.x*sc + sh;  v.y = v.y*sc + sh;
    v.z = v.z*sc + sh;  v.w = v.w*sc + sh;
    const float k = 0.70710678118654752f;
    v.x = 0.5f*v.x*(1.f + erff(v.x*k));
    v.y = 0.5f*v.y*(1.f + erff(v.y*k));
    v.z = 0.5f*v.z*(1.f + erff(v.z*k));
    v.w = 0.5f*v.w*(1.f + erff(v.w*k));
    ((float4*)out)[i] = v;
}

extern "C" void kernel_launch(void* const* d_in, const int* in_sizes, int n_in,
                              void* d_out, int out_size) {
    const float* x     = (const float*)d_in[0];
    const float* dww   = (const float*)d_in[1];
    const float* pww   = (const float*)d_in[2];
    const float* wgt   = (const float*)d_in[3];
    const float* bias  = (const float*)d_in[4];
    const float* gamma = (const float*)d_in[5];
    const float* beta  = (const float*)d_in[6];
    float* out = (float*)d_out;

    const int smA = (64*256 + 192*64 + 576) * 4;   // 116992 B
    const int smB = (64*256 + 64*64 + 64) * 4;     //  82176 B
    static bool attr_set = false;
    if (!attr_set) {
        cudaFuncSetAttribute(fused_dw_pw, cudaFuncAttributeMaxDynamicSharedMemorySize, smA);
        cudaFuncSetAttribute(sample_mm,   cudaFuncAttributeMaxDynamicSharedMemorySize, smB);
        attr_set = true;
    }

    fused_dw_pw<<<dim3(H_, B_), 256, smA>>>(x, dww, pww);
    sample_mm  <<<dim3(H_, B_), 256, smB>>>(x, wgt, bias);
    zero_stats <<<1, 64>>>();
    stats_kernel<<<B_*OC_, 256>>>();
    finalize_stats<<<1, 64>>>(gamma, beta);
    bn_gelu_kernel<<<TOT_/4/256, 256>>>(out);
}

// round 16
// speedup vs baseline: 1.0190x; 1.0190x over previous
#include <cuda_runtime.h>
#include <math.h>

#define B_  4
#define C_  64
#define OC_ 64
#define H_  256
#define W_  256
#define HW_ 65536
#define CHW_ (C_*HW_)          // 4194304
#define TOT_ (B_*CHW_)         // 16777216
#define MAXOFF_ 64.0f

// ---------------- scratch (device globals, no allocation) ----------------
__device__ float2 g_offp[B_*C_*HW_];    // paired (oy, ox) per channel
__device__ float  g_mod [TOT_];         // modulator
__device__ float  g_out [TOT_];         // pre-BN output
__device__ double g_sum  [OC_];
__device__ double g_sumsq[OC_];
__device__ float  g_scale[OC_];
__device__ float  g_shift[OC_];

// ---------------- f32x2 helpers ----------------
typedef unsigned long long u64;

__device__ __forceinline__ u64 pk2(float lo, float hi) {
    u64 r;
    asm("mov.b64 %0, {%1, %2};" : "=l"(r) : "f"(lo), "f"(hi));
    return r;
}
__device__ __forceinline__ void upk2(u64 v, float &lo, float &hi) {
    asm("mov.b64 {%0, %1}, %2;" : "=f"(lo), "=f"(hi) : "l"(v));
}
__device__ __forceinline__ void fma2(u64 &d, u64 a, u64 b) {
    asm("fma.rn.f32x2 %0, %1, %2, %0;" : "+l"(d) : "l"(a), "l"(b));
}

__device__ __forceinline__ float clipoff(float v) {
    return fminf(fmaxf(v, -MAXOFF_), MAXOFF_);
}

// ==========================================================================
// Kernel A: fused depthwise 3x3 conv -> pointwise 64->192 GEMM (f32x2)
// One block per (row h, batch b). 256 threads. smem: dw tile + pw weights.
// ==========================================================================
__global__ __launch_bounds__(256) void fused_dw_pw(const float* __restrict__ x,
                                                   const float* __restrict__ dww,
                                                   const float* __restrict__ pww) {
    extern __shared__ float smA[];
    float* s_in = smA;                  // [64][256] dw result, 65536 B
    float* s_pw = smA + 64*256;         // [192][64] pw weights, 49152 B
    float* s_dw = s_pw + 192*64;        // [64*9] dw weights

    const int tid = threadIdx.x;
    const int h = blockIdx.x, b = blockIdx.y;

    for (int i = tid; i < 192*64; i += 256) s_pw[i] = pww[i];
    for (int i = tid; i < 576;    i += 256) s_dw[i] = dww[i];
    __syncthreads();

    // ---- phase 1: depthwise conv for this row, all channels, into smem ----
    {
        const int p = tid;                       // p == w (full row per block)
        const float* xb = x + b*CHW_ + h*W_ + p; // channel 0 base at (h,p)
        #pragma unroll 2
        for (int c = 0; c < 64; c++) {
            const float* wp = s_dw + c*9;
            const float* xp = xb + c*HW_;
            float acc = 0.f;
            #pragma unroll
            for (int ky = 0; ky < 3; ky++) {
                int yy = h + ky - 1;
                if ((unsigned)yy >= H_) continue;
                const float* row = xp + (ky-1)*W_;
                if (p > 0)     acc = fmaf(__ldg(row - 1), wp[ky*3+0], acc);
                               acc = fmaf(__ldg(row    ), wp[ky*3+1], acc);
                if (p < W_-1)  acc = fmaf(__ldg(row + 1), wp[ky*3+2], acc);
            }
            s_in[c*256 + p] = acc;
        }
    }
    __syncthreads();

    // ---- phase 2: 192x64 GEMM with f32x2, thread tile = 4 pixels x 8 outs ----
    const int pg = tid & 63;      // pixel group: pixels 4*pg .. 4*pg+3
    const int og = tid >> 6;      // output group 0..3
    const int hwb = h*W_ + pg*4;
    const u64* sin64 = (const u64*)s_in;

    #pragma unroll 1
    for (int t = 0; t < 6; t++) {
        const int obase = t*32 + og*8;
        u64 acc0[8], acc1[8];
        #pragma unroll
        for (int j = 0; j < 8; j++) { acc0[j] = 0ULL; acc1[j] = 0ULL; }

        #pragma unroll
        for (int c4 = 0; c4 < 16; c4++) {
            float4 wq[8];
            #pragma unroll
            for (int j = 0; j < 8; j++)
                wq[j] = *(const float4*)(s_pw + (obase+j)*64 + c4*4);
            #pragma unroll
            for (int cc = 0; cc < 4; cc++) {
                const int c = c4*4 + cc;
                u64 a0 = sin64[(c*256 + pg*4    ) >> 1];
                u64 a1 = sin64[(c*256 + pg*4 + 2) >> 1];
                #pragma unroll
                for (int j = 0; j < 8; j++) {
                    float w = (cc == 0) ? wq[j].x : (cc == 1) ? wq[j].y
                            : (cc == 2) ? wq[j].z : wq[j].w;
                    u64 wd = pk2(w, w);
                    fma2(acc0[j], a0, wd);
                    fma2(acc1[j], a1, wd);
                }
            }
        }

        if (t < 4) {
            // outputs 0..127 -> clipped offsets, paired (oy=out[2c], ox=out[2c+1])
            #pragma unroll
            for (int jj = 0; jj < 4; jj++) {
                const int c = (obase >> 1) + jj;
                float y0,y1,y2,y3, xo0,xo1,xo2,xo3;
                upk2(acc0[2*jj  ], y0,  y1 );  upk2(acc1[2*jj  ], y2,  y3 );
                upk2(acc0[2*jj+1], xo0, xo1);  upk2(acc1[2*jj+1], xo2, xo3);
                float4* dst = (float4*)(g_offp + (b*64 + c)*HW_ + hwb);
                dst[0] = make_float4(clipoff(y0), clipoff(xo0), clipoff(y1), clipoff(xo1));
                dst[1] = make_float4(clipoff(y2), clipoff(xo2), clipoff(y3), clipoff(xo3));
            }
        } else {
            // outputs 128..191 -> modulator = 2*sigmoid
            #pragma unroll
            for (int j = 0; j < 8; j++) {
                const int m = obase - 128 + j;
                float v0,v1,v2,v3;
                upk2(acc0[j], v0, v1);  upk2(acc1[j], v2, v3);
                v0 = 2.f / (1.f + expf(-v0));
                v1 = 2.f / (1.f + expf(-v1));
                v2 = 2.f / (1.f + expf(-v2));
                v3 = 2.f / (1.f + expf(-v3));
                *(float4*)(g_mod + (b*64 + m)*HW_ + hwb) = make_float4(v0,v1,v2,v3);
            }
        }
    }
}

// ==========================================================================
// Kernel B: bilinear sample * modulator -> 64x64 GEMM (f32x2) + bias
// ==========================================================================
__device__ __forceinline__ float samp(const float* __restrict__ xc, int y, int xx) {
    if ((unsigned)y < H_ && (unsigned)xx < W_) return __ldg(xc + y*W_ + xx);
    return 0.f;
}

__global__ __launch_bounds__(256) void sample_mm(const float* __restrict__ x,
                                                 const float* __restrict__ wgt,
                                                 const float* __restrict__ bias) {
    extern __shared__ float smB[];
    float* s_s = smB;                // [64][256] sampled values, 65536 B
    float* s_w = smB + 64*256;       // [64][64] weights
    float* s_b = s_w + 64*64;        // [64] bias

    const int tid = threadIdx.x;
    const int h = blockIdx.x, b = blockIdx.y;

    for (int i = tid; i < 64*64; i += 256) s_w[i] = wgt[i];
    if (tid < 64) s_b[tid] = bias[tid];

    // ---- phase 1: sampling (1 pixel per thread, all 64 channels) ----
    {
        const int p = tid;
        const int hw = h*W_ + p;
        const float* xb = x + b*CHW_;
        #pragma unroll 2
        for (int c = 0; c < 64; c++) {
            float2 off = g_offp[(b*64 + c)*HW_ + hw];
            float  m   = __ldg(g_mod + (b*64 + c)*HW_ + hw);
            float yf = (float)h + off.x;
            float xf = (float)p + off.y;
            float y0f = floorf(yf), x0f = floorf(xf);
            float wy = yf - y0f,    wx = xf - x0f;
            int y0 = (int)y0f, x0 = (int)x0f;
            const float* xc = xb + c*HW_;
            float v00 = samp(xc, y0,   x0  );
            float v01 = samp(xc, y0,   x0+1);
            float v10 = samp(xc, y0+1, x0  );
            float v11 = samp(xc, y0+1, x0+1);
            float v = (1.f-wy)*((1.f-wx)*v00 + wx*v01)
                    +      wy *((1.f-wx)*v10 + wx*v11);
            s_s[c*256 + p] = v * m;
        }
    }
    __syncthreads();

    // ---- phase 2: 64x64 GEMM with f32x2, thread tile = 4 pixels x 8 outs ----
    const int pg = tid & 63;
    const int og = tid >> 6;
    const int hwb = h*W_ + pg*4;
    const u64* ss64 = (const u64*)s_s;

    #pragma unroll 1
    for (int t = 0; t < 2; t++) {
        const int obase = t*32 + og*8;
        u64 acc0[8], acc1[8];
        #pragma unroll
        for (int j = 0; j < 8; j++) {
            u64 bb = pk2(s_b[obase+j], s_b[obase+j]);
            acc0[j] = bb; acc1[j] = bb;
        }

        #pragma unroll
        for (int c4 = 0; c4 < 16; c4++) {
            float4 wq[8];
            #pragma unroll
            for (int j = 0; j < 8; j++)
                wq[j] = *(const float4*)(s_w + (obase+j)*64 + c4*4);
            #pragma unroll
            for (int cc = 0; cc < 4; cc++) {
                const int c = c4*4 + cc;
                u64 a0 = ss64[(c*256 + pg*4    ) >> 1];
                u64 a1 = ss64[(c*256 + pg*4 + 2) >> 1];
                #pragma unroll
                for (int j = 0; j < 8; j++) {
                    float w = (cc == 0) ? wq[j].x : (cc == 1) ? wq[j].y
                            : (cc == 2) ? wq[j].z : wq[j].w;
                    u64 wd = pk2(w, w);
                    fma2(acc0[j], a0, wd);
                    fma2(acc1[j], a1, wd);
                }
            }
        }

        #pragma unroll
        for (int j = 0; j < 8; j++) {
            const int o = obase + j;
            float v0,v1,v2,v3;
            upk2(acc0[j], v0, v1);  upk2(acc1[j], v2, v3);
            *(float4*)(g_out + (b*64 + o)*HW_ + hwb) = make_float4(v0,v1,v2,v3);
        }
    }
}

// ---------------- stats ----------------
__global__ void zero_stats() {
    if (threadIdx.x < OC_) { g_sum[threadIdx.x] = 0.0; g_sumsq[threadIdx.x] = 0.0; }
}

__global__ __launch_bounds__(256) void stats_kernel() {
    const int b = blockIdx.x >> 6;
    const int o = blockIdx.x & 63;
    const float4* pl = (const float4*)(g_out + (b*64 + o)*HW_);
    float s = 0.f, s2 = 0.f;
    for (int i = threadIdx.x; i < HW_/4; i += 256) {
        float4 v = pl[i];
        s  += v.x + v.y + v.z + v.w;
        s2 += v.x*v.x + v.y*v.y + v.z*v.z + v.w*v.w;
    }
    __shared__ double sh0[256];
    __shared__ double sh1[256];
    sh0[threadIdx.x] = (double)s; sh1[threadIdx.x] = (double)s2;
    __syncthreads();
    for (int st = 128; st > 0; st >>= 1) {
        if (threadIdx.x < st) {
            sh0[threadIdx.x] += sh0[threadIdx.x+st];
            sh1[threadIdx.x] += sh1[threadIdx.x+st];
        }
        __syncthreads();
    }
    if (threadIdx.x == 0) {
        atomicAdd(&g_sum[o],   sh0[0]);
        atomicAdd(&g_sumsq[o], sh1[0]);
    }
}

__global__ void finalize_stats(const float* __restrict__ gamma, const float* __restrict__ beta) {
    const int o = threadIdx.x;
    if (o < OC_) {
        double N = (double)B_ * (double)HW_;
        double mean = g_sum[o] / N;
        double var  = g_sumsq[o] / N - mean*mean;
        double inv  = 1.0 / sqrt(var + 1e-5);
        double gsc  = inv * (double)gamma[o];
        g_scale[o] = (float)gsc;
        g_shift[o] = (float)((double)beta[o] - mean * gsc);
    }
}

// ---------------- BN affine + exact GELU (float4) ----------------
__global__ __launch_bounds__(256) void bn_gelu_kernel(float* __restrict__ out) {
    const int i = blockIdx.x*256 + threadIdx.x;     // float4 index
    const int o = (i >> 14) & 63;                   // 16384 float4 per plane
    const float sc = g_scale[o], sh = g_shift[o];
    float4 v = ((const float4*)g_out)[i];
    v.x = v.x*sc + sh;  v.y = v.y*sc + sh;
    v.z = v.z*sc + sh;  v.w = v.w*sc + sh;
    const float k = 0.70710678118654752f;
    v.x = 0.5f*v.x*(1.f + erff(v.x*k));
    v.y = 0.5f*v.y*(1.f + erff(v.y*k));
    v.z = 0.5f*v.z*(1.f + erff(v.z*k));
    v.w = 0.5f*v.w*(1.f + erff(v.w*k));
    ((float4*)out)[i] = v;
}

extern "C" void kernel_launch(void* const* d_in, const int* in_sizes, int n_in,
                              void* d_out, int out_size) {
    const float* x     = (const float*)d_in[0];
    const float* dww   = (const float*)d_in[1];
    const float* pww   = (const float*)d_in[2];
    const float* wgt   = (const float*)d_in[3];
    const float* bias  = (const float*)d_in[4];
    const float* gamma = (const float*)d_in[5];
    const float* beta  = (const float*)d_in[6];
    float* out = (float*)d_out;

    const int smA = (64*256 + 192*64 + 576) * 4;   // 116992 B
    const int smB = (64*256 + 64*64 + 64) * 4;     //  82176 B
    static bool attr_set = false;
    if (!attr_set) {
        cudaFuncSetAttribute(fused_dw_pw, cudaFuncAttributeMaxDynamicSharedMemorySize, smA);
        cudaFuncSetAttribute(sample_mm,   cudaFuncAttributeMaxDynamicSharedMemorySize, smB);
        attr_set = true;
    }

    fused_dw_pw<<<dim3(H_, B_), 256, smA>>>(x, dww, pww);
    sample_mm  <<<dim3(H_, B_), 256, smB>>>(x, wgt, bias);
    zero_stats <<<1, 64>>>();
    stats_kernel<<<B_*OC_, 256>>>();
    finalize_stats<<<1, 64>>>(gamma, beta);
    bn_gelu_kernel<<<TOT_/4/256, 256>>>(out);
}